// round 15
// baseline (speedup 1.0000x reference)
#include <cuda_runtime.h>
#include <math.h>
#include <stdint.h>

#define Tn 2048
#define Hn 2048
#define Fn 512
#define En 64
#define Kn 8
#define Cn 320
#define F2n 1024
#define KTn (Kn*Tn)
#define NCHUNK 64
#define CHSZ 256

typedef unsigned int u32;
typedef unsigned long long u64;

// ---------------- scratch (device globals; zero-initialized at load) ----------------
__device__ float g_logits[Tn*En];
__device__ int   g_topi[KTn];       // [k*T + t]
__device__ float g_topv[KTn];
__device__ float g_probsum[En];
__device__ int   g_chunkcnt[NCHUNK*En];
__device__ int   g_basecnt[NCHUNK*En];
__device__ int   g_cnt[En];
__device__ int   g_totcnt[En];
__device__ int   g_tok[En*Cn];
__device__ float g_wslot[En*Cn];
__device__ int   g_slotmap[KTn];     // a=k*T+t -> e*Cn+slot, or -1 dropped
__device__ float g_hbuf[(size_t)En*Cn*Fn];   // gate raw, then relu(g)*u*w
__device__ float g_hs[(size_t)Tn*2*F2n];     // shared gate raw, then relu(g)*u
__device__ float g_ybuf[(size_t)En*Cn*Hn];   // expert down-proj per slot

// ---------------- packed f32x2 helpers (router logits GEMM stays exact fp32) --------
typedef unsigned long long ull;
__device__ __forceinline__ ull splat2(float a) {
    ull r; unsigned ai = __float_as_uint(a);
    asm("mov.b64 %0, {%1, %1};" : "=l"(r) : "r"(ai));
    return r;
}
__device__ __forceinline__ void ffma2(ull& d, ull a, ull b) {
    asm("fma.rn.f32x2 %0, %1, %2, %0;" : "+l"(d) : "l"(a), "l"(b));
}
__device__ __forceinline__ float2 unpk(ull v) {
    float2 f;
    asm("mov.b64 {%0, %1}, %2;" : "=f"(f.x), "=f"(f.y) : "l"(v));
    return f;
}

__device__ __forceinline__ void gemm1_core(
    const float* const* __restrict__ Arows,
    const float* __restrict__ B, int ldB, int Kd, int n0,
    ull acc[8], float* As, float* Bs)
{
    int tid = threadIdx.x;
    int tx = tid & 15, ty = tid >> 4;
    int lmA = tid >> 2, lkA = (tid & 3) << 2;
    int lkB = tid >> 4, lnB = (tid & 15) << 2;
    const float* Bp = B + (size_t)lkB * ldB + n0 + lnB;
    float4 av = *(const float4*)(Arows[lmA] + lkA);
    float4 bv = *(const float4*)(Bp);
    *(float4*)(As + lmA*16 + lkA) = av;
    *(float4*)(Bs + lkB*64 + lnB) = bv;
    __syncthreads();
    int nslab = Kd >> 4;
#pragma unroll 1
    for (int s = 0; s < nslab; s++) {
        int cur = s & 1, nxt = cur ^ 1;
        if (s + 1 < nslab) {
            av = *(const float4*)(Arows[lmA] + (s+1)*16 + lkA);
            bv = *(const float4*)(Bp + (size_t)(s+1)*16*ldB);
        }
        const float* Asc = As + cur*1024;
        const float* Bsc = Bs + cur*1024;
#pragma unroll
        for (int kk = 0; kk < 16; kk++) {
            ulonglong2 b = *(const ulonglong2*)(Bsc + kk*64 + (tx<<2));
#pragma unroll
            for (int i = 0; i < 4; i++) {
                ull a2 = splat2(Asc[(ty*4+i)*16 + kk]);
                ffma2(acc[i*2+0], a2, b.x);
                ffma2(acc[i*2+1], a2, b.y);
            }
        }
        if (s + 1 < nslab) {
            *(float4*)(As + nxt*1024 + lmA*16 + lkA) = av;
            *(float4*)(Bs + nxt*1024 + lkB*64 + lnB) = bv;
        }
        __syncthreads();
    }
}

// ---------------- router pipeline ----------------
__global__ void zero_kernel() {
    if (threadIdx.x < En) g_probsum[threadIdx.x] = 0.f;
}

__global__ __launch_bounds__(256) void logits_kernel(
    const float* __restrict__ x, const float* __restrict__ rw)
{
    __shared__ __align__(16) float As[2*64*16];
    __shared__ __align__(16) float Bs[2*16*64];
    __shared__ const float* Arows[64];
    int tid = threadIdx.x;
    int m0 = blockIdx.y * 64, n0 = blockIdx.x * 64;
    if (tid < 64) Arows[tid] = x + (size_t)(m0 + tid) * Hn;
    __syncthreads();
    ull acc[8] = {};
    gemm1_core(Arows, rw, En, Hn, n0, acc, As, Bs);
    int tx = tid & 15, ty = tid >> 4;
#pragma unroll
    for (int i = 0; i < 4; i++) {
        float2 p0 = unpk(acc[i*2+0]);
        float2 p1 = unpk(acc[i*2+1]);
        float4 r = make_float4(p0.x, p0.y, p1.x, p1.y);
        *(float4*)(g_logits + (size_t)(m0 + ty*4 + i)*En + n0 + (tx<<2)) = r;
    }
}

__global__ void router_post_kernel() {
    int t = blockIdx.x, tid = threadIdx.x;   // 64 threads
    __shared__ float sp[En];
    __shared__ float red[En];
    float l = g_logits[t*En + tid];
    red[tid] = l; __syncthreads();
    for (int s = 32; s > 0; s >>= 1) {
        if (tid < s) red[tid] = fmaxf(red[tid], red[tid+s]);
        __syncthreads();
    }
    float mx = red[0]; __syncthreads();
    float ex = expf(l - mx);
    red[tid] = ex; __syncthreads();
    for (int s = 32; s > 0; s >>= 1) {
        if (tid < s) red[tid] += red[tid+s];
        __syncthreads();
    }
    float p = ex / red[0];
    sp[tid] = p;
    atomicAdd(&g_probsum[tid], p);
    __syncthreads();
    if (tid == 0) {
        for (int k = 0; k < Kn; k++) {   // strict > keeps lowest index on ties
            float bv = -1.f; int bi = 0;
            for (int e = 0; e < En; e++) {
                float v = sp[e];
                if (v > bv) { bv = v; bi = e; }
            }
            g_topi[k*Tn + t] = bi;
            g_topv[k*Tn + t] = bv;
            sp[bi] = -1.f;
        }
    }
}

__global__ void hist_kernel() {
    __shared__ int cnt[En];
    int tid = threadIdx.x;
    if (tid < En) cnt[tid] = 0;
    __syncthreads();
    int a = blockIdx.x * CHSZ + tid;
    atomicAdd(&cnt[g_topi[a]], 1);
    __syncthreads();
    if (tid < En) g_chunkcnt[blockIdx.x*En + tid] = cnt[tid];
}

__global__ void scan_kernel() {
    int e = threadIdx.x;   // 64 threads
    int run = 0;
    for (int c = 0; c < NCHUNK; c++) {
        g_basecnt[c*En + e] = run;
        run += g_chunkcnt[c*En + e];
    }
    g_totcnt[e] = run;
    g_cnt[e] = run < Cn ? run : Cn;
}

__global__ void pos_kernel() {
    __shared__ int se[CHSZ];
    int tid = threadIdx.x;
    int a = blockIdx.x * CHSZ + tid;
    int e = g_topi[a];
    se[tid] = e;
    __syncthreads();
    int rank = 0;
    for (int j = 0; j < tid; j++) rank += (se[j] == e);
    int slot = g_basecnt[blockIdx.x*En + e] + rank;
    if (slot < Cn) {
        int t = a & (Tn - 1);          // a = k*T + t
        g_tok[e*Cn + slot] = t;
        g_wslot[e*Cn + slot] = g_topv[a];
        g_slotmap[a] = e*Cn + slot;
    } else {
        g_slotmap[a] = -1;
    }
}

__global__ void aux_kernel(float* __restrict__ out, int write_aux) {
    __shared__ float red[En];
    int e = threadIdx.x;
    red[e] = (float)g_totcnt[e] * g_probsum[e];
    __syncthreads();
    for (int s = 32; s > 0; s >>= 1) {
        if (e < s) red[e] += red[e+s];
        __syncthreads();
    }
    if (e == 0 && write_aux)
        out[(size_t)Tn*Hn] = (float)En * red[0] / ((float)Tn * (float)Kn * (float)Tn);
}

// gather-combine: out[t] += sum over this token's slots of g_ybuf[slot]
__global__ __launch_bounds__(256) void combine_kernel(float* __restrict__ out) {
    __shared__ int sl[Kn];
    int t = blockIdx.x, tid = threadIdx.x;
    if (tid < Kn) sl[tid] = g_slotmap[tid*Tn + t];
    __syncthreads();
#pragma unroll
    for (int it = 0; it < Hn/(256*4); it++) {
        int c = (it*256 + tid) * 4;
        float4 v = *(float4*)(out + (size_t)t*Hn + c);
#pragma unroll
        for (int k = 0; k < Kn; k++) {
            int s = sl[k];
            if (s >= 0) {
                float4 y = *(const float4*)(g_ybuf + (size_t)s*Hn + c);
                v.x += y.x; v.y += y.y; v.z += y.z; v.w += y.w;
            }
        }
        *(float4*)(out + (size_t)t*Hn + c) = v;
    }
}

// ============ fp16 mma.sync m16n8k16, 64x64 warp tiles, 256 threads ============
__device__ __forceinline__ u32 h2pack(float lo, float hi){
    u32 r; asm("cvt.rn.f16x2.f32 %0, %1, %2;" : "=r"(r) : "f"(hi), "f"(lo));
    return r;   // low 16 = lo, high 16 = hi
}
__device__ __forceinline__ void mma16(float* c, u32 a0, u32 a1, u32 a2, u32 a3,
                                      u32 b0, u32 b1){
    asm volatile("mma.sync.aligned.m16n8k16.row.col.f32.f16.f16.f32 "
        "{%0,%1,%2,%3}, {%4,%5,%6,%7}, {%8,%9}, {%0,%1,%2,%3};"
        : "+f"(c[0]),"+f"(c[1]),"+f"(c[2]),"+f"(c[3])
        : "r"(a0),"r"(a1),"r"(a2),"r"(a3),"r"(b0),"r"(b1));
}
#define KEYOF(r) ((u32)(((r) ^ ((r) >> 2)) & 3))

// Row layout (SROW=40 u32): pair j (k=2j,2j+1) of kstep-group q=j>>3 lives at
// 8q + 2*((j&3)^key) + 4*((j>>2)&1)-interleave via (pk[i],pk[i+4]) uint2 stores.
#define SROW 40
#define A_PL (128*SROW)          // 5120 u32
#define B_PL (256*SROW)          // 10240 u32
#define BUFU (A_PL + B_PL)       // 15360 u32
#define SMB  (2*BUFU*4)          // 122880 bytes

// MODE 0: shared gate  A=x           B=swg[e], ldB=F2n -> g_hs raw
// MODE 1: shared up    A=x           B=swu[e]          -> g_hs = relu(g)*u
// MODE 2: expert gate  A=x gathered  B=wg[e],  ldB=Fn  -> g_hbuf raw   (rows<cnt)
// MODE 3: expert up    A=x gathered  B=wu[e]           -> g_hbuf=relu(g)*u*w
// MODE 4: shared down  A=g_hs        B=swd,    ldB=Hn  -> out plain store
// MODE 5: expert down  A=g_hbuf      B=wd[e],  ldB=Hn  -> g_ybuf plain store
template<int MODE>
__global__ __launch_bounds__(256, 1) void mm_s(
    const float* __restrict__ X, const float* __restrict__ B,
    float* __restrict__ out)
{
    extern __shared__ u32 sm[];
    int tid = threadIdx.x, lane = tid & 31, wid = tid >> 5;
    int warp_m = wid & 1, warp_n = wid >> 1;     // 2 x 4 warps, warp tile 64x64
    int e = blockIdx.z;
    int m0 = blockIdx.y * 128, n0 = blockIdx.x * 256;

    int cnt = Tn, Kd = Hn, ldB = F2n;
    const float* Bp0 = B;
    if (MODE == 0 || MODE == 1) { Bp0 = B + (size_t)e*Hn*F2n; }
    if (MODE == 2 || MODE == 3) {
        cnt = g_cnt[e]; if (m0 >= cnt) return;
        ldB = Fn; Bp0 = B + (size_t)e*Hn*Fn;
    }
    if (MODE == 4) { Kd = 2*F2n; ldB = Hn; }
    if (MODE == 5) {
        cnt = g_cnt[e]; if (m0 >= cnt) return;
        Kd = Fn; ldB = Hn; Bp0 = B + (size_t)e*Fn*Hn;
    }

    // A staging: 2 threads per row; thread handles quarters aq = (tid&1)*2 + c
    int arow = tid >> 1;
    u32 keyA = KEYOF(arow);
    const float* rp;
    if (MODE <= 1) rp = X + (size_t)(m0 + arow) * Hn;
    else if (MODE <= 3) {
        int m = m0 + arow;
        int tk = (m < cnt) ? g_tok[e*Cn + m] : 0;
        rp = X + (size_t)tk * Hn;
    } else if (MODE == 4) rp = g_hs + (size_t)(m0 + arow) * (2*F2n);
    else {
        int m = m0 + arow; if (m > Cn-1) m = Cn-1;   // rows>=cnt guarded at store
        rp = g_hbuf + ((size_t)e*Cn + m) * Fn;
    }

    // B staging: 1 thread per n column (256), 4 chunks of 16 k's
    int bn = tid;
    u32 keyB = KEYOF(bn);
    const float* bp = Bp0 + n0 + bn;

    float acc[4][8][4];
#pragma unroll
    for (int i = 0; i < 4; i++)
#pragma unroll
    for (int j = 0; j < 8; j++)
#pragma unroll
    for (int q = 0; q < 4; q++) acc[i][j][q] = 0.f;

    float va[16], vb[16];

#define LDA(s,c) do{ \
    const float4* _a = (const float4*)(rp + (size_t)(s)*64 + ((tid&1)*2 + (c))*16); \
    _Pragma("unroll") for (int j = 0; j < 4; j++) *(float4*)(va + j*4) = _a[j]; }while(0)
#define LDB(s,h) do{ const float* _b = bp + ((size_t)(s)*64 + (h)*16)*ldB; \
    _Pragma("unroll") for (int j = 0; j < 16; j++) vb[j] = _b[(size_t)j*ldB]; }while(0)
#define STOA(bsel,c) do{ \
    u32* Ah = sm + (bsel)*BUFU; \
    u32 pk[8]; \
    _Pragma("unroll") for (int m = 0; m < 8; m++) pk[m] = h2pack(va[2*m], va[2*m+1]); \
    u32 rb = (u32)arow*SROW + 8u*((u32)(tid&1)*2u + (u32)(c)); \
    _Pragma("unroll") for (int i = 0; i < 4; i++){ \
        *(uint2*)(Ah + rb + 2*(((u32)i)^keyA)) = make_uint2(pk[i], pk[i+4]); } \
}while(0)
#define STOB(bsel,h) do{ \
    u32* Bsm = sm + (bsel)*BUFU + A_PL; \
    u32 pk[8]; \
    _Pragma("unroll") for (int m = 0; m < 8; m++) pk[m] = h2pack(vb[2*m], vb[2*m+1]); \
    u32 rb = (u32)bn*SROW + 8u*(u32)(h); \
    _Pragma("unroll") for (int i = 0; i < 4; i++){ \
        *(uint2*)(Bsm + rb + 2*(((u32)i)^keyB)) = make_uint2(pk[i], pk[i+4]); } \
}while(0)
// one kstep: load 4 A frag pairs + per-nt B frag, 32 MMA
#define MMA1(c) do{ \
    uint2 a02[4], a13[4]; \
    _Pragma("unroll") for (int mt = 0; mt < 4; mt++){ \
        int r1 = warp_m*64 + mt*16 + grp; \
        int r2 = r1 + 8; \
        a02[mt] = *(const uint2*)(Ah + (u32)r1*SROW + 8*(c) + 2*(((u32)tig)^KEYOF(r1))); \
        a13[mt] = *(const uint2*)(Ah + (u32)r2*SROW + 8*(c) + 2*(((u32)tig)^KEYOF(r2))); \
    } \
    _Pragma("unroll") for (int nt = 0; nt < 8; nt++){ \
        int nr = warp_n*64 + nt*8 + grp; \
        uint2 bf = *(const uint2*)(Bsm + (u32)nr*SROW + 8*(c) + 2*(((u32)tig)^KEYOF(nr))); \
        _Pragma("unroll") for (int mt = 0; mt < 4; mt++) \
            mma16(acc[mt][nt], a02[mt].x, a13[mt].x, a02[mt].y, a13[mt].y, bf.x, bf.y); \
    } \
}while(0)

    LDA(0,0); STOA(0,0);
    LDA(0,1); STOA(0,1);
    LDB(0,0); STOB(0,0);
    LDB(0,1); STOB(0,1);
    LDB(0,2); STOB(0,2);
    LDB(0,3); STOB(0,3);
    __syncthreads();

    int nslab = Kd >> 6;                 // K = 64 per slab
    int grp = lane >> 2, tig = lane & 3;
#pragma unroll 1
    for (int s = 0; s < nslab; s++) {
        int nxt = (s + 1) & 1;
        bool more = (s + 1 < nslab);
        const u32* Ah = sm + (s & 1)*BUFU;
        const u32* Bsm = Ah + A_PL;
        if (more) { LDA(s+1, 0); LDB(s+1, 0); }
        MMA1(0);
        if (more) { STOA(nxt, 0); STOB(nxt, 0); LDA(s+1, 1); LDB(s+1, 1); }
        MMA1(1);
        if (more) { STOA(nxt, 1); STOB(nxt, 1); LDB(s+1, 2); }
        MMA1(2);
        if (more) { STOB(nxt, 2); LDB(s+1, 3); }
        MMA1(3);
        if (more) { STOB(nxt, 3); }
        __syncthreads();
    }

    // epilogue
#pragma unroll
    for (int mt = 0; mt < 4; mt++) {
#pragma unroll
        for (int half = 0; half < 2; half++) {
            int row = warp_m*64 + mt*16 + grp + half*8;
            int gr = m0 + row;
            bool ok = true;
            float w = 1.f;
            if (MODE == 2 || MODE == 3 || MODE == 5) ok = (gr < cnt);
            if (MODE == 3 && ok) w = g_wslot[e*Cn + gr];
#pragma unroll
            for (int nt = 0; nt < 8; nt++) {
                float c0 = acc[mt][nt][half*2+0];
                float c1 = acc[mt][nt][half*2+1];
                int col = n0 + warp_n*64 + nt*8 + tig*2;
                if (MODE == 0) {
                    *(float2*)(g_hs + (size_t)gr*(2*F2n) + (size_t)e*F2n + col) =
                        make_float2(c0, c1);
                } else if (MODE == 1) {
                    float2* p = (float2*)(g_hs + (size_t)gr*(2*F2n) + (size_t)e*F2n + col);
                    float2 g = *p;
                    *p = make_float2(fmaxf(g.x, 0.f)*c0, fmaxf(g.y, 0.f)*c1);
                } else if (MODE == 2) {
                    if (ok)
                        *(float2*)(g_hbuf + ((size_t)e*Cn + gr)*Fn + col) =
                            make_float2(c0, c1);
                } else if (MODE == 3) {
                    if (ok) {
                        float2* p = (float2*)(g_hbuf + ((size_t)e*Cn + gr)*Fn + col);
                        float2 g = *p;
                        *p = make_float2(fmaxf(g.x, 0.f)*c0*w, fmaxf(g.y, 0.f)*c1*w);
                    }
                } else if (MODE == 4) {
                    *(float2*)(out + (size_t)gr*Hn + col) = make_float2(c0, c1);
                } else {
                    if (ok)
                        *(float2*)(g_ybuf + ((size_t)e*Cn + gr)*Hn + col) =
                            make_float2(c0, c1);
                }
            }
        }
    }
#undef LDA
#undef LDB
#undef STOA
#undef STOB
#undef MMA1
}

// ---------------- launch ----------------
extern "C" void kernel_launch(void* const* d_in, const int* in_sizes, int n_in,
                              void* d_out, int out_size) {
    const float* x   = (const float*)d_in[0];
    const float* rw  = (const float*)d_in[1];
    const float* wg  = (const float*)d_in[2];
    const float* wu  = (const float*)d_in[3];
    const float* wd  = (const float*)d_in[4];
    const float* swg = (const float*)d_in[5];
    const float* swu = (const float*)d_in[6];
    const float* swd = (const float*)d_in[7];
    float* out = (float*)d_out;

    cudaFuncSetAttribute(mm_s<0>, cudaFuncAttributeMaxDynamicSharedMemorySize, SMB);
    cudaFuncSetAttribute(mm_s<1>, cudaFuncAttributeMaxDynamicSharedMemorySize, SMB);
    cudaFuncSetAttribute(mm_s<2>, cudaFuncAttributeMaxDynamicSharedMemorySize, SMB);
    cudaFuncSetAttribute(mm_s<3>, cudaFuncAttributeMaxDynamicSharedMemorySize, SMB);
    cudaFuncSetAttribute(mm_s<4>, cudaFuncAttributeMaxDynamicSharedMemorySize, SMB);
    cudaFuncSetAttribute(mm_s<5>, cudaFuncAttributeMaxDynamicSharedMemorySize, SMB);

    // mm_s<0> as 4th launch so the profiler samples a GEMM
    zero_kernel<<<1, 64>>>();
    logits_kernel<<<dim3(En/64, Tn/64), 256>>>(x, rw);
    router_post_kernel<<<Tn, 64>>>();
    mm_s<0><<<dim3(F2n/256, Tn/128, 2), 256, SMB>>>(x, swg, out);   // 4th launch
    hist_kernel<<<NCHUNK, CHSZ>>>();
    scan_kernel<<<1, En>>>();
    pos_kernel<<<NCHUNK, CHSZ>>>();
    mm_s<1><<<dim3(F2n/256, Tn/128, 2), 256, SMB>>>(x, swu, out);
    // expert gate -> expert up (fuses relu(g)*u*w into g_hbuf)
    mm_s<2><<<dim3(Fn/256, (Cn+127)/128, En), 256, SMB>>>(x, wg, out);
    mm_s<3><<<dim3(Fn/256, (Cn+127)/128, En), 256, SMB>>>(x, wu, out);
    // shared down initializes out; expert down -> per-slot rows; combine gathers
    mm_s<4><<<dim3(Hn/256, Tn/128, 1), 256, SMB>>>(x, swd, out);
    mm_s<5><<<dim3(Hn/256, (Cn+127)/128, En), 256, SMB>>>(x, wd, out);
    combine_kernel<<<Tn, 256>>>(out);

    int write_aux = (out_size > Tn*Hn) ? 1 : 0;
    aux_kernel<<<1, En>>>(out, write_aux);
}

// round 16
// speedup vs baseline: 1.2225x; 1.2225x over previous
#include <cuda_runtime.h>
#include <cuda_fp16.h>
#include <math.h>
#include <stdint.h>

#define Tn 2048
#define Hn 2048
#define Fn 512
#define En 64
#define Kn 8
#define Cn 320
#define F2n 1024
#define KTn (Kn*Tn)
#define NCHUNK 64
#define CHSZ 256

typedef unsigned int u32;
typedef unsigned long long u64;

// ---------------- scratch (device globals; zero-initialized at load) ----------------
__device__ float g_logits[Tn*En];
__device__ int   g_topi[KTn];       // [k*T + t]
__device__ float g_topv[KTn];
__device__ float g_probsum[En];
__device__ int   g_chunkcnt[NCHUNK*En];
__device__ int   g_basecnt[NCHUNK*En];
__device__ int   g_cnt[En];
__device__ int   g_totcnt[En];
__device__ int   g_tok[En*Cn];
__device__ float g_wslot[En*Cn];
__device__ int   g_slotmap[KTn];     // a=k*T+t -> e*Cn+slot, or -1 dropped
__device__ u32   g_xh[(size_t)Tn*Hn/2];        // x as packed fp16 pairs
__device__ u32   g_hs_h[(size_t)Tn*F2n];       // shared hidden, packed fp16 (gate raw then relu*u)
__device__ u32   g_hbuf_h[(size_t)En*Cn*(Fn/2)]; // expert hidden, packed fp16
__device__ float g_ybuf[(size_t)En*Cn*Hn];     // expert down-proj per slot (fp32)

// ---------------- packed f32x2 helpers (router logits GEMM stays exact fp32) --------
typedef unsigned long long ull;
__device__ __forceinline__ ull splat2(float a) {
    ull r; unsigned ai = __float_as_uint(a);
    asm("mov.b64 %0, {%1, %1};" : "=l"(r) : "r"(ai));
    return r;
}
__device__ __forceinline__ void ffma2(ull& d, ull a, ull b) {
    asm("fma.rn.f32x2 %0, %1, %2, %0;" : "+l"(d) : "l"(a), "l"(b));
}
__device__ __forceinline__ float2 unpk(ull v) {
    float2 f;
    asm("mov.b64 {%0, %1}, %2;" : "=f"(f.x), "=f"(f.y) : "l"(v));
    return f;
}

__device__ __forceinline__ void gemm1_core(
    const float* const* __restrict__ Arows,
    const float* __restrict__ B, int ldB, int Kd, int n0,
    ull acc[8], float* As, float* Bs)
{
    int tid = threadIdx.x;
    int tx = tid & 15, ty = tid >> 4;
    int lmA = tid >> 2, lkA = (tid & 3) << 2;
    int lkB = tid >> 4, lnB = (tid & 15) << 2;
    const float* Bp = B + (size_t)lkB * ldB + n0 + lnB;
    float4 av = *(const float4*)(Arows[lmA] + lkA);
    float4 bv = *(const float4*)(Bp);
    *(float4*)(As + lmA*16 + lkA) = av;
    *(float4*)(Bs + lkB*64 + lnB) = bv;
    __syncthreads();
    int nslab = Kd >> 4;
#pragma unroll 1
    for (int s = 0; s < nslab; s++) {
        int cur = s & 1, nxt = cur ^ 1;
        if (s + 1 < nslab) {
            av = *(const float4*)(Arows[lmA] + (s+1)*16 + lkA);
            bv = *(const float4*)(Bp + (size_t)(s+1)*16*ldB);
        }
        const float* Asc = As + cur*1024;
        const float* Bsc = Bs + cur*1024;
#pragma unroll
        for (int kk = 0; kk < 16; kk++) {
            ulonglong2 b = *(const ulonglong2*)(Bsc + kk*64 + (tx<<2));
#pragma unroll
            for (int i = 0; i < 4; i++) {
                ull a2 = splat2(Asc[(ty*4+i)*16 + kk]);
                ffma2(acc[i*2+0], a2, b.x);
                ffma2(acc[i*2+1], a2, b.y);
            }
        }
        if (s + 1 < nslab) {
            *(float4*)(As + nxt*1024 + lmA*16 + lkA) = av;
            *(float4*)(Bs + nxt*1024 + lkB*64 + lnB) = bv;
        }
        __syncthreads();
    }
}

// ---------------- fp16 helpers ----------------
__device__ __forceinline__ u32 h2pack(float lo, float hi){
    u32 r; asm("cvt.rn.f16x2.f32 %0, %1, %2;" : "=r"(r) : "f"(hi), "f"(lo));
    return r;   // low 16 = lo, high 16 = hi
}

// ---------------- router pipeline ----------------
__global__ void zero_kernel() {
    if (threadIdx.x < En) g_probsum[threadIdx.x] = 0.f;
}

// x -> packed fp16 (8 floats per thread)
__global__ __launch_bounds__(256) void cvtx_kernel(const float* __restrict__ x) {
    int i = blockIdx.x*256 + threadIdx.x;
    const float4* p = (const float4*)x + (size_t)i*2;
    float4 a = p[0], b = p[1];
    uint4 o;
    o.x = h2pack(a.x, a.y); o.y = h2pack(a.z, a.w);
    o.z = h2pack(b.x, b.y); o.w = h2pack(b.z, b.w);
    ((uint4*)g_xh)[i] = o;
}

__global__ __launch_bounds__(256) void logits_kernel(
    const float* __restrict__ x, const float* __restrict__ rw)
{
    __shared__ __align__(16) float As[2*64*16];
    __shared__ __align__(16) float Bs[2*16*64];
    __shared__ const float* Arows[64];
    int tid = threadIdx.x;
    int m0 = blockIdx.y * 64, n0 = blockIdx.x * 64;
    if (tid < 64) Arows[tid] = x + (size_t)(m0 + tid) * Hn;
    __syncthreads();
    ull acc[8] = {};
    gemm1_core(Arows, rw, En, Hn, n0, acc, As, Bs);
    int tx = tid & 15, ty = tid >> 4;
#pragma unroll
    for (int i = 0; i < 4; i++) {
        float2 p0 = unpk(acc[i*2+0]);
        float2 p1 = unpk(acc[i*2+1]);
        float4 r = make_float4(p0.x, p0.y, p1.x, p1.y);
        *(float4*)(g_logits + (size_t)(m0 + ty*4 + i)*En + n0 + (tx<<2)) = r;
    }
}

__global__ void router_post_kernel() {
    int t = blockIdx.x, tid = threadIdx.x;   // 64 threads
    __shared__ float sp[En];
    __shared__ float red[En];
    float l = g_logits[t*En + tid];
    red[tid] = l; __syncthreads();
    for (int s = 32; s > 0; s >>= 1) {
        if (tid < s) red[tid] = fmaxf(red[tid], red[tid+s]);
        __syncthreads();
    }
    float mx = red[0]; __syncthreads();
    float ex = expf(l - mx);
    red[tid] = ex; __syncthreads();
    for (int s = 32; s > 0; s >>= 1) {
        if (tid < s) red[tid] += red[tid+s];
        __syncthreads();
    }
    float p = ex / red[0];
    sp[tid] = p;
    atomicAdd(&g_probsum[tid], p);
    __syncthreads();
    if (tid == 0) {
        for (int k = 0; k < Kn; k++) {   // strict > keeps lowest index on ties
            float bv = -1.f; int bi = 0;
            for (int e = 0; e < En; e++) {
                float v = sp[e];
                if (v > bv) { bv = v; bi = e; }
            }
            g_topi[k*Tn + t] = bi;
            g_topv[k*Tn + t] = bv;
            sp[bi] = -1.f;
        }
    }
}

__global__ void hist_kernel() {
    __shared__ int cnt[En];
    int tid = threadIdx.x;
    if (tid < En) cnt[tid] = 0;
    __syncthreads();
    int a = blockIdx.x * CHSZ + tid;
    atomicAdd(&cnt[g_topi[a]], 1);
    __syncthreads();
    if (tid < En) g_chunkcnt[blockIdx.x*En + tid] = cnt[tid];
}

__global__ void scan_kernel() {
    int e = threadIdx.x;   // 64 threads
    int run = 0;
    for (int c = 0; c < NCHUNK; c++) {
        g_basecnt[c*En + e] = run;
        run += g_chunkcnt[c*En + e];
    }
    g_totcnt[e] = run;
    g_cnt[e] = run < Cn ? run : Cn;
}

__global__ void pos_kernel() {
    __shared__ int se[CHSZ];
    int tid = threadIdx.x;
    int a = blockIdx.x * CHSZ + tid;
    int e = g_topi[a];
    se[tid] = e;
    __syncthreads();
    int rank = 0;
    for (int j = 0; j < tid; j++) rank += (se[j] == e);
    int slot = g_basecnt[blockIdx.x*En + e] + rank;
    if (slot < Cn) {
        int t = a & (Tn - 1);          // a = k*T + t
        g_tok[e*Cn + slot] = t;
        g_wslot[e*Cn + slot] = g_topv[a];
        g_slotmap[a] = e*Cn + slot;
    } else {
        g_slotmap[a] = -1;
    }
}

__global__ void aux_kernel(float* __restrict__ out, int write_aux) {
    __shared__ float red[En];
    int e = threadIdx.x;
    red[e] = (float)g_totcnt[e] * g_probsum[e];
    __syncthreads();
    for (int s = 32; s > 0; s >>= 1) {
        if (e < s) red[e] += red[e+s];
        __syncthreads();
    }
    if (e == 0 && write_aux)
        out[(size_t)Tn*Hn] = (float)En * red[0] / ((float)Tn * (float)Kn * (float)Tn);
}

// gather-combine: out[t] += sum over this token's slots of g_ybuf[slot]
__global__ __launch_bounds__(256) void combine_kernel(float* __restrict__ out) {
    __shared__ int sl[Kn];
    int t = blockIdx.x, tid = threadIdx.x;
    if (tid < Kn) sl[tid] = g_slotmap[tid*Tn + t];
    __syncthreads();
#pragma unroll
    for (int it = 0; it < Hn/(256*4); it++) {
        int c = (it*256 + tid) * 4;
        float4 v = *(float4*)(out + (size_t)t*Hn + c);
#pragma unroll
        for (int k = 0; k < Kn; k++) {
            int s = sl[k];
            if (s >= 0) {
                float4 y = *(const float4*)(g_ybuf + (size_t)s*Hn + c);
                v.x += y.x; v.y += y.y; v.z += y.z; v.w += y.w;
            }
        }
        *(float4*)(out + (size_t)t*Hn + c) = v;
    }
}

// ====== fp16 mma.sync m16n8k16, CTA 128x128, 256 thr, 2 CTAs/SM, K=64 slabs ======
__device__ __forceinline__ void mma16(float* c, u32 a0, u32 a1, u32 a2, u32 a3,
                                      u32 b0, u32 b1){
    asm volatile("mma.sync.aligned.m16n8k16.row.col.f32.f16.f16.f32 "
        "{%0,%1,%2,%3}, {%4,%5,%6,%7}, {%8,%9}, {%0,%1,%2,%3};"
        : "+f"(c[0]),"+f"(c[1]),"+f"(c[2]),"+f"(c[3])
        : "r"(a0),"r"(a1),"r"(a2),"r"(a3),"r"(b0),"r"(b1));
}
#define KEYOF(r) ((u32)(((r) ^ ((r) >> 2)) & 3))

#define SROW 40
#define A_PL (128*SROW)          // 5120 u32
#define B_PL (128*SROW)          // 5120 u32
#define BUFU (A_PL + B_PL)       // 10240 u32
#define SMB  (2*BUFU*4)          // 81920 bytes/CTA; 2 CTAs = 160KB/SM

// MODE 0: shared gate  A=g_xh        B=swg[e], ldB=F2n -> g_hs_h raw fp16
// MODE 1: shared up    A=g_xh        B=swu[e]          -> g_hs_h = relu(g)*u fp16
// MODE 2: expert gate  A=g_xh gather B=wg[e],  ldB=Fn  -> g_hbuf_h raw (rows<cnt)
// MODE 3: expert up    A=g_xh gather B=wu[e]           -> g_hbuf_h=relu(g)*u*w fp16
// MODE 4: shared down  A=g_hs_h      B=swd,    ldB=Hn  -> out plain store fp32
// MODE 5: expert down  A=g_hbuf_h    B=wd[e],  ldB=Hn  -> g_ybuf plain store fp32
template<int MODE>
__global__ __launch_bounds__(256, 2) void mm_s(
    const float* __restrict__ B, float* __restrict__ out)
{
    extern __shared__ u32 sm[];
    int tid = threadIdx.x, lane = tid & 31, wid = tid >> 5;
    int warp_m = wid & 3, warp_n = wid >> 2;     // 4 x 2 warps, warp tile 32x64
    int e = blockIdx.z;
    int m0 = blockIdx.y * 128, n0 = blockIdx.x * 128;

    int cnt = Tn, Kd = Hn, ldB = F2n;
    const float* Bp0 = B;
    if (MODE == 0 || MODE == 1) { Bp0 = B + (size_t)e*Hn*F2n; }
    if (MODE == 2 || MODE == 3) {
        cnt = g_cnt[e]; if (m0 >= cnt) return;
        ldB = Fn; Bp0 = B + (size_t)e*Hn*Fn;
    }
    if (MODE == 4) { Kd = 2*F2n; ldB = Hn; }
    if (MODE == 5) {
        cnt = g_cnt[e]; if (m0 >= cnt) return;
        Kd = Fn; ldB = Hn; Bp0 = B + (size_t)e*Fn*Hn;
    }

    // A staging from packed-fp16 planes: 2 threads per row, each 32 halves (16 u32)
    // in 2 chunks of 8 u32 (chunk c -> kstep-group quarter (tid&1)*2 + c)
    int arow = tid >> 1;
    u32 keyA = KEYOF(arow);
    const u32* rp;
    if (MODE <= 1) rp = g_xh + (size_t)(m0 + arow) * (Hn/2);
    else if (MODE <= 3) {
        int m = m0 + arow;
        int tk = (m < cnt) ? g_tok[e*Cn + m] : 0;
        rp = g_xh + (size_t)tk * (Hn/2);
    } else if (MODE == 4) rp = g_hs_h + (size_t)(m0 + arow) * F2n;
    else {
        int m = m0 + arow; if (m > Cn-1) m = Cn-1;   // rows>=cnt guarded at store
        rp = g_hbuf_h + (size_t)(e*Cn + m) * (Fn/2);
    }

    // B staging (fp32 gmem): 2 threads per n column; half bkh covers k[32bkh,+32)
    int bn = tid & 127, bkh = tid >> 7;
    u32 keyB = KEYOF(bn);
    const float* bp = Bp0 + n0 + bn;

    float acc[2][8][4];
#pragma unroll
    for (int i = 0; i < 2; i++)
#pragma unroll
    for (int j = 0; j < 8; j++)
#pragma unroll
    for (int q = 0; q < 4; q++) acc[i][j][q] = 0.f;

    u32  va[8];
    float vb[16];

#define LDA(s,c) do{ \
    const uint4* _a = (const uint4*)(rp + (size_t)(s)*32 + ((tid&1)*2 + (c))*8); \
    *(uint4*)(va+0) = _a[0]; *(uint4*)(va+4) = _a[1]; }while(0)
#define LDB(s,h) do{ \
    const float* _b = bp + ((size_t)(s)*64 + bkh*32 + (h)*16)*ldB; \
    _Pragma("unroll") for (int j = 0; j < 16; j++) vb[j] = _b[(size_t)j*ldB]; }while(0)
#define STOA(bsel,c) do{ \
    u32* Ah = sm + (bsel)*BUFU; \
    u32 rb = (u32)arow*SROW + 8u*((u32)(tid&1)*2u + (u32)(c)); \
    _Pragma("unroll") for (int i = 0; i < 4; i++){ \
        *(uint2*)(Ah + rb + 2*(((u32)i)^keyA)) = make_uint2(va[i], va[i+4]); } \
}while(0)
#define STOB(bsel,h) do{ \
    u32* Bsm = sm + (bsel)*BUFU + A_PL; \
    u32 pk[8]; \
    _Pragma("unroll") for (int m = 0; m < 8; m++) pk[m] = h2pack(vb[2*m], vb[2*m+1]); \
    u32 rb = (u32)bn*SROW + 16u*(u32)bkh + 8u*(u32)(h); \
    _Pragma("unroll") for (int i = 0; i < 4; i++){ \
        *(uint2*)(Bsm + rb + 2*(((u32)i)^keyB)) = make_uint2(pk[i], pk[i+4]); } \
}while(0)
#define MMA1(c) do{ \
    uint2 a02[2], a13[2]; \
    _Pragma("unroll") for (int mt = 0; mt < 2; mt++){ \
        int r1 = warp_m*32 + mt*16 + grp; \
        int r2 = r1 + 8; \
        a02[mt] = *(const uint2*)(Ah + (u32)r1*SROW + 8*(c) + 2*(((u32)tig)^KEYOF(r1))); \
        a13[mt] = *(const uint2*)(Ah + (u32)r2*SROW + 8*(c) + 2*(((u32)tig)^KEYOF(r2))); \
    } \
    _Pragma("unroll") for (int nt = 0; nt < 8; nt++){ \
        int nr = warp_n*64 + nt*8 + grp; \
        uint2 bf = *(const uint2*)(Bsm + (u32)nr*SROW + 8*(c) + 2*(((u32)tig)^KEYOF(nr))); \
        mma16(acc[0][nt], a02[0].x, a13[0].x, a02[0].y, a13[0].y, bf.x, bf.y); \
        mma16(acc[1][nt], a02[1].x, a13[1].x, a02[1].y, a13[1].y, bf.x, bf.y); \
    } \
}while(0)

    LDA(0,0); STOA(0,0);
    LDA(0,1); STOA(0,1);
    LDB(0,0); STOB(0,0);
    LDB(0,1); STOB(0,1);
    __syncthreads();

    int nslab = Kd >> 6;                 // K = 64 per slab
    int grp = lane >> 2, tig = lane & 3;
#pragma unroll 1
    for (int s = 0; s < nslab; s++) {
        int nxt = (s + 1) & 1;
        bool more = (s + 1 < nslab);
        const u32* Ah = sm + (s & 1)*BUFU;
        const u32* Bsm = Ah + A_PL;
        if (more) { LDA(s+1, 0); LDB(s+1, 0); }
        MMA1(0);
        if (more) { STOA(nxt, 0); STOB(nxt, 0); LDA(s+1, 1); LDB(s+1, 1); }
        MMA1(1);
        if (more) { STOA(nxt, 1); STOB(nxt, 1); }
        MMA1(2);
        MMA1(3);
        __syncthreads();
    }

    // epilogue
#pragma unroll
    for (int mt = 0; mt < 2; mt++) {
#pragma unroll
        for (int half = 0; half < 2; half++) {
            int row = warp_m*32 + mt*16 + grp + half*8;
            int gr = m0 + row;
            bool ok = true;
            float w = 1.f;
            if (MODE == 2 || MODE == 3 || MODE == 5) ok = (gr < cnt);
            if (MODE == 3 && ok) w = g_wslot[e*Cn + gr];
#pragma unroll
            for (int nt = 0; nt < 8; nt++) {
                float c0 = acc[mt][nt][half*2+0];
                float c1 = acc[mt][nt][half*2+1];
                int col = n0 + warp_n*64 + nt*8 + tig*2;
                if (MODE == 0) {
                    size_t idx = (size_t)gr*F2n + (((size_t)e*F2n + col) >> 1);
                    g_hs_h[idx] = h2pack(c0, c1);
                } else if (MODE == 1) {
                    size_t idx = (size_t)gr*F2n + (((size_t)e*F2n + col) >> 1);
                    u32 gv = g_hs_h[idx];
                    __half2 hg = *reinterpret_cast<__half2*>(&gv);
                    float2 gf = __half22float2(hg);
                    g_hs_h[idx] = h2pack(fmaxf(gf.x, 0.f)*c0, fmaxf(gf.y, 0.f)*c1);
                } else if (MODE == 2) {
                    if (ok) {
                        size_t idx = (size_t)(e*Cn + gr)*(Fn/2) + (col >> 1);
                        g_hbuf_h[idx] = h2pack(c0, c1);
                    }
                } else if (MODE == 3) {
                    if (ok) {
                        size_t idx = (size_t)(e*Cn + gr)*(Fn/2) + (col >> 1);
                        u32 gv = g_hbuf_h[idx];
                        __half2 hg = *reinterpret_cast<__half2*>(&gv);
                        float2 gf = __half22float2(hg);
                        g_hbuf_h[idx] = h2pack(fmaxf(gf.x, 0.f)*c0*w,
                                               fmaxf(gf.y, 0.f)*c1*w);
                    }
                } else if (MODE == 4) {
                    *(float2*)(out + (size_t)gr*Hn + col) = make_float2(c0, c1);
                } else {
                    if (ok)
                        *(float2*)(g_ybuf + ((size_t)e*Cn + gr)*Hn + col) =
                            make_float2(c0, c1);
                }
            }
        }
    }
#undef LDA
#undef LDB
#undef STOA
#undef STOB
#undef MMA1
}

// ---------------- launch ----------------
extern "C" void kernel_launch(void* const* d_in, const int* in_sizes, int n_in,
                              void* d_out, int out_size) {
    const float* x   = (const float*)d_in[0];
    const float* rw  = (const float*)d_in[1];
    const float* wg  = (const float*)d_in[2];
    const float* wu  = (const float*)d_in[3];
    const float* wd  = (const float*)d_in[4];
    const float* swg = (const float*)d_in[5];
    const float* swu = (const float*)d_in[6];
    const float* swd = (const float*)d_in[7];
    float* out = (float*)d_out;

    cudaFuncSetAttribute(mm_s<0>, cudaFuncAttributeMaxDynamicSharedMemorySize, SMB);
    cudaFuncSetAttribute(mm_s<1>, cudaFuncAttributeMaxDynamicSharedMemorySize, SMB);
    cudaFuncSetAttribute(mm_s<2>, cudaFuncAttributeMaxDynamicSharedMemorySize, SMB);
    cudaFuncSetAttribute(mm_s<3>, cudaFuncAttributeMaxDynamicSharedMemorySize, SMB);
    cudaFuncSetAttribute(mm_s<4>, cudaFuncAttributeMaxDynamicSharedMemorySize, SMB);
    cudaFuncSetAttribute(mm_s<5>, cudaFuncAttributeMaxDynamicSharedMemorySize, SMB);

    // mm_s<0> as 4th launch so the profiler samples a GEMM
    zero_kernel<<<1, 64>>>();
    cvtx_kernel<<<Tn*Hn/(8*256), 256>>>(x);
    logits_kernel<<<dim3(En/64, Tn/64), 256>>>(x, rw);
    mm_s<0><<<dim3(F2n/128, Tn/128, 2), 256, SMB>>>(swg, out);   // 4th launch
    router_post_kernel<<<Tn, 64>>>();
    hist_kernel<<<NCHUNK, CHSZ>>>();
    scan_kernel<<<1, En>>>();
    pos_kernel<<<NCHUNK, CHSZ>>>();
    mm_s<1><<<dim3(F2n/128, Tn/128, 2), 256, SMB>>>(swu, out);
    // expert gate -> expert up (fuses relu(g)*u*w into g_hbuf_h)
    mm_s<2><<<dim3(Fn/128, (Cn+127)/128, En), 256, SMB>>>(wg, out);
    mm_s<3><<<dim3(Fn/128, (Cn+127)/128, En), 256, SMB>>>(wu, out);
    // shared down initializes out; expert down -> per-slot rows; combine gathers
    mm_s<4><<<dim3(Hn/128, Tn/128, 1), 256, SMB>>>(swd, out);
    mm_s<5><<<dim3(Hn/128, (Cn+127)/128, En), 256, SMB>>>(wd, out);
    combine_kernel<<<Tn, 256>>>(out);

    int write_aux = (out_size > Tn*Hn) ? 1 : 0;
    aux_kernel<<<1, En>>>(out, write_aux);
}

// round 17
// speedup vs baseline: 1.3150x; 1.0756x over previous
#include <cuda_runtime.h>
#include <cuda_fp16.h>
#include <math.h>
#include <stdint.h>

#define Tn 2048
#define Hn 2048
#define Fn 512
#define En 64
#define Kn 8
#define Cn 320
#define F2n 1024
#define KTn (Kn*Tn)
#define NCHUNK 64
#define CHSZ 256

typedef unsigned int u32;
typedef unsigned long long u64;

// ---------------- scratch (device globals; zero-initialized at load) ----------------
__device__ float g_logits[Tn*En];
__device__ int   g_topi[KTn];       // [k*T + t]
__device__ float g_topv[KTn];
__device__ float g_probsum[En];
__device__ int   g_chunkcnt[NCHUNK*En];
__device__ int   g_basecnt[NCHUNK*En];
__device__ int   g_cnt[En];
__device__ int   g_totcnt[En];
__device__ int   g_tok[En*Cn];
__device__ float g_wslot[En*Cn];
__device__ int   g_slotmap[KTn];     // a=k*T+t -> e*Cn+slot, or -1 dropped
__device__ u32   g_xh[(size_t)Tn*Hn/2];          // x as packed fp16 pairs
__device__ u32   g_hs_h[(size_t)Tn*F2n];         // shared hidden, packed fp16
__device__ u32   g_hbuf_h[(size_t)En*Cn*(Fn/2)]; // expert hidden, packed fp16
__device__ float g_ybuf[(size_t)En*Cn*Hn];       // expert down-proj per slot (fp32)

// ---------------- packed f32x2 helpers (router logits GEMM stays exact fp32) --------
typedef unsigned long long ull;
__device__ __forceinline__ ull splat2(float a) {
    ull r; unsigned ai = __float_as_uint(a);
    asm("mov.b64 %0, {%1, %1};" : "=l"(r) : "r"(ai));
    return r;
}
__device__ __forceinline__ void ffma2(ull& d, ull a, ull b) {
    asm("fma.rn.f32x2 %0, %1, %2, %0;" : "+l"(d) : "l"(a), "l"(b));
}
__device__ __forceinline__ float2 unpk(ull v) {
    float2 f;
    asm("mov.b64 {%0, %1}, %2;" : "=f"(f.x), "=f"(f.y) : "l"(v));
    return f;
}

__device__ __forceinline__ void gemm1_core(
    const float* const* __restrict__ Arows,
    const float* __restrict__ B, int ldB, int Kd, int n0,
    ull acc[8], float* As, float* Bs)
{
    int tid = threadIdx.x;
    int tx = tid & 15, ty = tid >> 4;
    int lmA = tid >> 2, lkA = (tid & 3) << 2;
    int lkB = tid >> 4, lnB = (tid & 15) << 2;
    const float* Bp = B + (size_t)lkB * ldB + n0 + lnB;
    float4 av = *(const float4*)(Arows[lmA] + lkA);
    float4 bv = *(const float4*)(Bp);
    *(float4*)(As + lmA*16 + lkA) = av;
    *(float4*)(Bs + lkB*64 + lnB) = bv;
    __syncthreads();
    int nslab = Kd >> 4;
#pragma unroll 1
    for (int s = 0; s < nslab; s++) {
        int cur = s & 1, nxt = cur ^ 1;
        if (s + 1 < nslab) {
            av = *(const float4*)(Arows[lmA] + (s+1)*16 + lkA);
            bv = *(const float4*)(Bp + (size_t)(s+1)*16*ldB);
        }
        const float* Asc = As + cur*1024;
        const float* Bsc = Bs + cur*1024;
#pragma unroll
        for (int kk = 0; kk < 16; kk++) {
            ulonglong2 b = *(const ulonglong2*)(Bsc + kk*64 + (tx<<2));
#pragma unroll
            for (int i = 0; i < 4; i++) {
                ull a2 = splat2(Asc[(ty*4+i)*16 + kk]);
                ffma2(acc[i*2+0], a2, b.x);
                ffma2(acc[i*2+1], a2, b.y);
            }
        }
        if (s + 1 < nslab) {
            *(float4*)(As + nxt*1024 + lmA*16 + lkA) = av;
            *(float4*)(Bs + nxt*1024 + lkB*64 + lnB) = bv;
        }
        __syncthreads();
    }
}

// ---------------- fp16 helpers ----------------
__device__ __forceinline__ u32 h2pack(float lo, float hi){
    u32 r; asm("cvt.rn.f16x2.f32 %0, %1, %2;" : "=r"(r) : "f"(hi), "f"(lo));
    return r;   // low 16 = lo, high 16 = hi
}

// ---------------- router pipeline ----------------
__global__ void zero_kernel() {
    if (threadIdx.x < En) g_probsum[threadIdx.x] = 0.f;
}

// x -> packed fp16 (8 floats per thread)
__global__ __launch_bounds__(256) void cvtx_kernel(const float* __restrict__ x) {
    int i = blockIdx.x*256 + threadIdx.x;
    const float4* p = (const float4*)x + (size_t)i*2;
    float4 a = p[0], b = p[1];
    uint4 o;
    o.x = h2pack(a.x, a.y); o.y = h2pack(a.z, a.w);
    o.z = h2pack(b.x, b.y); o.w = h2pack(b.z, b.w);
    ((uint4*)g_xh)[i] = o;
}

__global__ __launch_bounds__(256) void logits_kernel(
    const float* __restrict__ x, const float* __restrict__ rw)
{
    __shared__ __align__(16) float As[2*64*16];
    __shared__ __align__(16) float Bs[2*16*64];
    __shared__ const float* Arows[64];
    int tid = threadIdx.x;
    int m0 = blockIdx.y * 64, n0 = blockIdx.x * 64;
    if (tid < 64) Arows[tid] = x + (size_t)(m0 + tid) * Hn;
    __syncthreads();
    ull acc[8] = {};
    gemm1_core(Arows, rw, En, Hn, n0, acc, As, Bs);
    int tx = tid & 15, ty = tid >> 4;
#pragma unroll
    for (int i = 0; i < 4; i++) {
        float2 p0 = unpk(acc[i*2+0]);
        float2 p1 = unpk(acc[i*2+1]);
        float4 r = make_float4(p0.x, p0.y, p1.x, p1.y);
        *(float4*)(g_logits + (size_t)(m0 + ty*4 + i)*En + n0 + (tx<<2)) = r;
    }
}

__global__ void router_post_kernel() {
    int t = blockIdx.x, tid = threadIdx.x;   // 64 threads
    __shared__ float sp[En];
    __shared__ float red[En];
    float l = g_logits[t*En + tid];
    red[tid] = l; __syncthreads();
    for (int s = 32; s > 0; s >>= 1) {
        if (tid < s) red[tid] = fmaxf(red[tid], red[tid+s]);
        __syncthreads();
    }
    float mx = red[0]; __syncthreads();
    float ex = expf(l - mx);
    red[tid] = ex; __syncthreads();
    for (int s = 32; s > 0; s >>= 1) {
        if (tid < s) red[tid] += red[tid+s];
        __syncthreads();
    }
    float p = ex / red[0];
    sp[tid] = p;
    atomicAdd(&g_probsum[tid], p);
    __syncthreads();
    if (tid == 0) {
        for (int k = 0; k < Kn; k++) {   // strict > keeps lowest index on ties
            float bv = -1.f; int bi = 0;
            for (int e = 0; e < En; e++) {
                float v = sp[e];
                if (v > bv) { bv = v; bi = e; }
            }
            g_topi[k*Tn + t] = bi;
            g_topv[k*Tn + t] = bv;
            sp[bi] = -1.f;
        }
    }
}

__global__ void hist_kernel() {
    __shared__ int cnt[En];
    int tid = threadIdx.x;
    if (tid < En) cnt[tid] = 0;
    __syncthreads();
    int a = blockIdx.x * CHSZ + tid;
    atomicAdd(&cnt[g_topi[a]], 1);
    __syncthreads();
    if (tid < En) g_chunkcnt[blockIdx.x*En + tid] = cnt[tid];
}

__global__ void scan_kernel() {
    int e = threadIdx.x;   // 64 threads
    int run = 0;
    for (int c = 0; c < NCHUNK; c++) {
        g_basecnt[c*En + e] = run;
        run += g_chunkcnt[c*En + e];
    }
    g_totcnt[e] = run;
    g_cnt[e] = run < Cn ? run : Cn;
}

__global__ void pos_kernel() {
    __shared__ int se[CHSZ];
    int tid = threadIdx.x;
    int a = blockIdx.x * CHSZ + tid;
    int e = g_topi[a];
    se[tid] = e;
    __syncthreads();
    int rank = 0;
    for (int j = 0; j < tid; j++) rank += (se[j] == e);
    int slot = g_basecnt[blockIdx.x*En + e] + rank;
    if (slot < Cn) {
        int t = a & (Tn - 1);          // a = k*T + t
        g_tok[e*Cn + slot] = t;
        g_wslot[e*Cn + slot] = g_topv[a];
        g_slotmap[a] = e*Cn + slot;
    } else {
        g_slotmap[a] = -1;
    }
}

__global__ void aux_kernel(float* __restrict__ out, int write_aux) {
    __shared__ float red[En];
    int e = threadIdx.x;
    red[e] = (float)g_totcnt[e] * g_probsum[e];
    __syncthreads();
    for (int s = 32; s > 0; s >>= 1) {
        if (e < s) red[e] += red[e+s];
        __syncthreads();
    }
    if (e == 0 && write_aux)
        out[(size_t)Tn*Hn] = (float)En * red[0] / ((float)Tn * (float)Kn * (float)Tn);
}

// gather-combine: out[t] += sum over this token's slots of g_ybuf[slot]
__global__ __launch_bounds__(256) void combine_kernel(float* __restrict__ out) {
    __shared__ int sl[Kn];
    int t = blockIdx.x, tid = threadIdx.x;
    if (tid < Kn) sl[tid] = g_slotmap[tid*Tn + t];
    __syncthreads();
#pragma unroll
    for (int it = 0; it < Hn/(256*4); it++) {
        int c = (it*256 + tid) * 4;
        float4 v = *(float4*)(out + (size_t)t*Hn + c);
#pragma unroll
        for (int k = 0; k < Kn; k++) {
            int s = sl[k];
            if (s >= 0) {
                float4 y = *(const float4*)(g_ybuf + (size_t)s*Hn + c);
                v.x += y.x; v.y += y.y; v.z += y.z; v.w += y.w;
            }
        }
        *(float4*)(out + (size_t)t*Hn + c) = v;
    }
}

// ====== fp16 mma.sync m16n8k16 + ldmatrix + cp.async; CTA 128x128, 2 CTAs/SM ======
__device__ __forceinline__ void mma16(float* c, u32 a0, u32 a1, u32 a2, u32 a3,
                                      u32 b0, u32 b1){
    asm volatile("mma.sync.aligned.m16n8k16.row.col.f32.f16.f16.f32 "
        "{%0,%1,%2,%3}, {%4,%5,%6,%7}, {%8,%9}, {%0,%1,%2,%3};"
        : "+f"(c[0]),"+f"(c[1]),"+f"(c[2]),"+f"(c[3])
        : "r"(a0),"r"(a1),"r"(a2),"r"(a3),"r"(b0),"r"(b1));
}
__device__ __forceinline__ void ldsm4(u32& r0, u32& r1, u32& r2, u32& r3, u32 addr){
    asm volatile("ldmatrix.sync.aligned.m8n8.x4.shared.b16 {%0,%1,%2,%3}, [%4];"
        : "=r"(r0),"=r"(r1),"=r"(r2),"=r"(r3) : "r"(addr));
}
#define CPA(dst,src)  asm volatile("cp.async.ca.shared.global [%0], [%1], 16;"::"r"(dst),"l"(src):"memory")
#define CPA_COMMIT()  asm volatile("cp.async.commit_group;":::"memory")
#define CPA_WAIT()    asm volatile("cp.async.wait_group 0;":::"memory")

// Row layout: SROW=40 u32; row data = 8 chunks of 16B (K=64 halves);
// chunk c of row r lives at u32 offset 40r + 4*(c ^ (r&7)).
#define SROW 40
#define A_PL (128*SROW)          // 5120 u32
#define B_PL (128*SROW)          // 5120 u32
#define BUFU (A_PL + B_PL)       // 10240 u32
#define SMB  (2*BUFU*4)          // 81920 bytes/CTA; 2 CTAs = 160KB/SM

// MODE 0: shared gate  A=g_xh        B=swg[e], ldB=F2n -> g_hs_h raw fp16
// MODE 1: shared up    A=g_xh        B=swu[e]          -> g_hs_h = relu(g)*u fp16
// MODE 2: expert gate  A=g_xh gather B=wg[e],  ldB=Fn  -> g_hbuf_h raw (rows<cnt)
// MODE 3: expert up    A=g_xh gather B=wu[e]           -> g_hbuf_h=relu(g)*u*w fp16
// MODE 4: shared down  A=g_hs_h      B=swd,    ldB=Hn  -> out plain store fp32
// MODE 5: expert down  A=g_hbuf_h    B=wd[e],  ldB=Hn  -> g_ybuf plain store fp32
template<int MODE>
__global__ __launch_bounds__(256, 2) void mm_s(
    const float* __restrict__ B, float* __restrict__ out)
{
    extern __shared__ u32 sm[];
    int tid = threadIdx.x, lane = tid & 31, wid = tid >> 5;
    int warp_m = wid & 3, warp_n = wid >> 2;     // 4 x 2 warps, warp tile 32x64
    int e = blockIdx.z;
    int m0 = blockIdx.y * 128, n0 = blockIdx.x * 128;

    int cnt = Tn, Kd = Hn, ldB = F2n;
    const float* Bp0 = B;
    if (MODE == 0 || MODE == 1) { Bp0 = B + (size_t)e*Hn*F2n; }
    if (MODE == 2 || MODE == 3) {
        cnt = g_cnt[e]; if (m0 >= cnt) return;
        ldB = Fn; Bp0 = B + (size_t)e*Hn*Fn;
    }
    if (MODE == 4) { Kd = 2*F2n; ldB = Hn; }
    if (MODE == 5) {
        cnt = g_cnt[e]; if (m0 >= cnt) return;
        Kd = Fn; ldB = Hn; Bp0 = B + (size_t)e*Fn*Hn;
    }

    u32 smb = (u32)__cvta_generic_to_shared(sm);

    // A staging via cp.async: 2 threads per row; half h covers chunks 4h..4h+3
    int arow = tid >> 1, h = tid & 1;
    u32 keyA = (u32)(arow & 7);
    const u32* rp;
    if (MODE <= 1) rp = g_xh + (size_t)(m0 + arow) * (Hn/2);
    else if (MODE <= 3) {
        int m = m0 + arow;
        int tk = (m < cnt) ? g_tok[e*Cn + m] : 0;
        rp = g_xh + (size_t)tk * (Hn/2);
    } else if (MODE == 4) rp = g_hs_h + (size_t)(m0 + arow) * F2n;
    else {
        int m = m0 + arow; if (m > Cn-1) m = Cn-1;   // rows>=cnt guarded at store
        rp = g_hbuf_h + (size_t)(e*Cn + m) * (Fn/2);
    }

    // B staging (fp32 gmem): 2 threads per n column; half bkh covers k[32bkh,+32)
    int bn = tid & 127, bkh = tid >> 7;
    u32 keyB = (u32)(bn & 7);
    const float* bp = Bp0 + n0 + bn;

    // fragment LDSM address components (per lane)
    int grp = lane >> 2, tig = lane & 3;
    u32 laneHiA = (u32)(lane >> 4);                       // A: chunk +0/+1
    u32 hiB = (u32)((lane >> 3) & 1);                     // B: chunk +0/+1
    u32 aOff[2], aKey[2];
#pragma unroll
    for (int mt = 0; mt < 2; mt++) {
        int r = warp_m*32 + mt*16 + ((lane>>3)&1)*8 + (lane&7);
        aOff[mt] = 160u*(u32)r; aKey[mt] = (u32)(r & 7);
    }
    u32 bOff[4], bKey[4];
#pragma unroll
    for (int np = 0; np < 4; np++) {
        int r = warp_n*64 + np*16 + ((lane>>4)<<3) + (lane&7);
        bOff[np] = 160u*(u32)r; bKey[np] = (u32)(r & 7);
    }

    float acc[2][8][4];
#pragma unroll
    for (int i = 0; i < 2; i++)
#pragma unroll
    for (int j = 0; j < 8; j++)
#pragma unroll
    for (int q = 0; q < 4; q++) acc[i][j][q] = 0.f;

    float vb[16];

#define STAGEA(bsel,s) do{ \
    const char* _src = (const char*)(rp + (size_t)(s)*32 + h*16); \
    u32 _dst = smb + (u32)(bsel)*(BUFU*4) + 160u*(u32)arow; \
    _Pragma("unroll") for (int j = 0; j < 4; j++){ \
        u32 d = _dst + 16u*(((u32)(4*h + j)) ^ keyA); \
        CPA(d, _src + j*16); } \
}while(0)
#define LDB(s,q) do{ \
    const float* _b = bp + ((size_t)(s)*64 + bkh*32 + (q)*16)*ldB; \
    _Pragma("unroll") for (int j = 0; j < 16; j++) vb[j] = _b[(size_t)j*ldB]; }while(0)
#define STOB(bsel,q) do{ \
    u32 pk[8]; \
    _Pragma("unroll") for (int m = 0; m < 8; m++) pk[m] = h2pack(vb[2*m], vb[2*m+1]); \
    u32* Bsm = sm + (bsel)*BUFU + A_PL + 40u*(u32)bn; \
    u32 c0 = 4u*(u32)bkh + 2u*(u32)(q); \
    *(uint4*)(Bsm + 4*((c0  )^keyB)) = make_uint4(pk[0],pk[1],pk[2],pk[3]); \
    *(uint4*)(Bsm + 4*((c0+1)^keyB)) = make_uint4(pk[4],pk[5],pk[6],pk[7]); \
}while(0)
#define MMA1(c) do{ \
    u32 x0,x1,x2,x3, y0,y1,y2,y3; \
    ldsm4(x0,x1,x2,x3, Ahb + aOff[0] + 16u*((2u*(c)+laneHiA)^aKey[0])); \
    ldsm4(y0,y1,y2,y3, Ahb + aOff[1] + 16u*((2u*(c)+laneHiA)^aKey[1])); \
    _Pragma("unroll") for (int np = 0; np < 4; np++){ \
        u32 b0,b1,b2,b3; \
        ldsm4(b0,b1,b2,b3, Bhb + bOff[np] + 16u*((2u*(c)+hiB)^bKey[np])); \
        mma16(acc[0][2*np+0], x0,x1,x2,x3, b0,b1); \
        mma16(acc[1][2*np+0], y0,y1,y2,y3, b0,b1); \
        mma16(acc[0][2*np+1], x0,x1,x2,x3, b2,b3); \
        mma16(acc[1][2*np+1], y0,y1,y2,y3, b2,b3); \
    } \
}while(0)

    // prologue: stage slab 0
    STAGEA(0, 0);
    CPA_COMMIT();
    LDB(0,0); STOB(0,0);
    LDB(0,1); STOB(0,1);
    CPA_WAIT();
    __syncthreads();

    int nslab = Kd >> 6;                 // K = 64 per slab
#pragma unroll 1
    for (int s = 0; s < nslab; s++) {
        int nxt = (s + 1) & 1;
        bool more = (s + 1 < nslab);
        u32 Ahb = smb + (u32)(s & 1)*(BUFU*4);
        u32 Bhb = Ahb + A_PL*4;
        if (more) { STAGEA(nxt, s+1); CPA_COMMIT(); LDB(s+1, 0); }
        MMA1(0);
        if (more) { STOB(nxt, 0); LDB(s+1, 1); }
        MMA1(1);
        if (more) { STOB(nxt, 1); }
        MMA1(2);
        MMA1(3);
        if (more) CPA_WAIT();
        __syncthreads();
    }

    // epilogue
#pragma unroll
    for (int mt = 0; mt < 2; mt++) {
#pragma unroll
        for (int half = 0; half < 2; half++) {
            int row = warp_m*32 + mt*16 + grp + half*8;
            int gr = m0 + row;
            bool ok = true;
            float w = 1.f;
            if (MODE == 2 || MODE == 3 || MODE == 5) ok = (gr < cnt);
            if (MODE == 3 && ok) w = g_wslot[e*Cn + gr];
#pragma unroll
            for (int nt = 0; nt < 8; nt++) {
                float c0 = acc[mt][nt][half*2+0];
                float c1 = acc[mt][nt][half*2+1];
                int col = n0 + warp_n*64 + nt*8 + tig*2;
                if (MODE == 0) {
                    size_t idx = (size_t)gr*F2n + (((size_t)e*F2n + col) >> 1);
                    g_hs_h[idx] = h2pack(c0, c1);
                } else if (MODE == 1) {
                    size_t idx = (size_t)gr*F2n + (((size_t)e*F2n + col) >> 1);
                    u32 gv = g_hs_h[idx];
                    __half2 hg = *reinterpret_cast<__half2*>(&gv);
                    float2 gf = __half22float2(hg);
                    g_hs_h[idx] = h2pack(fmaxf(gf.x, 0.f)*c0, fmaxf(gf.y, 0.f)*c1);
                } else if (MODE == 2) {
                    if (ok) {
                        size_t idx = (size_t)(e*Cn + gr)*(Fn/2) + (col >> 1);
                        g_hbuf_h[idx] = h2pack(c0, c1);
                    }
                } else if (MODE == 3) {
                    if (ok) {
                        size_t idx = (size_t)(e*Cn + gr)*(Fn/2) + (col >> 1);
                        u32 gv = g_hbuf_h[idx];
                        __half2 hg = *reinterpret_cast<__half2*>(&gv);
                        float2 gf = __half22float2(hg);
                        g_hbuf_h[idx] = h2pack(fmaxf(gf.x, 0.f)*c0*w,
                                               fmaxf(gf.y, 0.f)*c1*w);
                    }
                } else if (MODE == 4) {
                    *(float2*)(out + (size_t)gr*Hn + col) = make_float2(c0, c1);
                } else {
                    if (ok)
                        *(float2*)(g_ybuf + ((size_t)e*Cn + gr)*Hn + col) =
                            make_float2(c0, c1);
                }
            }
        }
    }
#undef STAGEA
#undef LDB
#undef STOB
#undef MMA1
}

// ---------------- launch ----------------
extern "C" void kernel_launch(void* const* d_in, const int* in_sizes, int n_in,
                              void* d_out, int out_size) {
    const float* x   = (const float*)d_in[0];
    const float* rw  = (const float*)d_in[1];
    const float* wg  = (const float*)d_in[2];
    const float* wu  = (const float*)d_in[3];
    const float* wd  = (const float*)d_in[4];
    const float* swg = (const float*)d_in[5];
    const float* swu = (const float*)d_in[6];
    const float* swd = (const float*)d_in[7];
    float* out = (float*)d_out;

    cudaFuncSetAttribute(mm_s<0>, cudaFuncAttributeMaxDynamicSharedMemorySize, SMB);
    cudaFuncSetAttribute(mm_s<1>, cudaFuncAttributeMaxDynamicSharedMemorySize, SMB);
    cudaFuncSetAttribute(mm_s<2>, cudaFuncAttributeMaxDynamicSharedMemorySize, SMB);
    cudaFuncSetAttribute(mm_s<3>, cudaFuncAttributeMaxDynamicSharedMemorySize, SMB);
    cudaFuncSetAttribute(mm_s<4>, cudaFuncAttributeMaxDynamicSharedMemorySize, SMB);
    cudaFuncSetAttribute(mm_s<5>, cudaFuncAttributeMaxDynamicSharedMemorySize, SMB);

    // mm_s<0> as 4th launch so the profiler samples a GEMM
    zero_kernel<<<1, 64>>>();
    cvtx_kernel<<<Tn*Hn/(8*256), 256>>>(x);
    logits_kernel<<<dim3(En/64, Tn/64), 256>>>(x, rw);
    mm_s<0><<<dim3(F2n/128, Tn/128, 2), 256, SMB>>>(swg, out);   // 4th launch
    router_post_kernel<<<Tn, 64>>>();
    hist_kernel<<<NCHUNK, CHSZ>>>();
    scan_kernel<<<1, En>>>();
    pos_kernel<<<NCHUNK, CHSZ>>>();
    mm_s<1><<<dim3(F2n/128, Tn/128, 2), 256, SMB>>>(swu, out);
    // expert gate -> expert up (fuses relu(g)*u*w into g_hbuf_h)
    mm_s<2><<<dim3(Fn/128, (Cn+127)/128, En), 256, SMB>>>(wg, out);
    mm_s<3><<<dim3(Fn/128, (Cn+127)/128, En), 256, SMB>>>(wu, out);
    // shared down initializes out; expert down -> per-slot rows; combine gathers
    mm_s<4><<<dim3(Hn/128, Tn/128, 1), 256, SMB>>>(swd, out);
    mm_s<5><<<dim3(Hn/128, (Cn+127)/128, En), 256, SMB>>>(wd, out);
    combine_kernel<<<Tn, 256>>>(out);

    int write_aux = (out_size > Tn*Hn) ? 1 : 0;
    aux_kernel<<<1, En>>>(out, write_aux);
}